// round 14
// baseline (speedup 1.0000x reference)
#include <cuda_runtime.h>
#include <cstdint>
#include <float.h>

// DiffGatedTopK: x [N=16384, D=4096] fp32.
// k = int(D*0.15) = 614. out = x * topk_mask * (sigmoid(top1-top2)*3 + 1)

#define DCOLS 4096
#define KSEL  614
#define NT    512
#define NW    16          // warps per block
#define GAIN_C 3.0f
#define CAP   32

// float <-> order-preserving unsigned key (fallback / top-2 reduce only)
__device__ __forceinline__ unsigned f2k_f(float f) {
    unsigned u = __float_as_uint(f);
    return u ^ ((unsigned)(((int)u) >> 31) | 0x80000000u);
}
__device__ __forceinline__ float k2f(unsigned k) {
    unsigned b = (k & 0x80000000u) ? (k ^ 0x80000000u) : ~k;
    return __uint_as_float(b);
}

__device__ __forceinline__ int warp_incl_scan(int v, int lane) {
    #pragma unroll
    for (int o = 1; o < 32; o <<= 1) {
        int n = __shfl_up_sync(0xFFFFFFFFu, v, o);
        if (lane >= o) v += n;
    }
    return v;
}

// count of the 8 register-resident values >= t
#define CNT8_GE(t, res) do {                                             \
    int _c = 0;                                                          \
    _c += (r0.x >= (t)) + (r0.y >= (t)) + (r0.z >= (t)) + (r0.w >= (t));\
    _c += (r1.x >= (t)) + (r1.y >= (t)) + (r1.z >= (t)) + (r1.w >= (t));\
    (res) = _c; } while (0)

// block reduce: tree over 16 per-warp partials stored in buf
#define TREE16(buf, res) do {                                            \
    int _v = (lane < NW) ? (buf)[lane] : 0;                              \
    _v += __shfl_down_sync(0xFFFFFFFFu, _v, 8);                          \
    _v += __shfl_down_sync(0xFFFFFFFFu, _v, 4);                          \
    _v += __shfl_down_sync(0xFFFFFFFFu, _v, 2);                          \
    _v += __shfl_down_sync(0xFFFFFFFFu, _v, 1);                          \
    (res) = __shfl_sync(0xFFFFFFFFu, _v, 0); } while (0)

__global__ void __launch_bounds__(NT, 4)
diff_gated_topk_kernel(const float* __restrict__ x, float* __restrict__ out) {
    const int tid  = threadIdx.x;
    const int lane = tid & 31;
    const int wid  = tid >> 5;

    const float4* __restrict__ xr =
        reinterpret_cast<const float4*>(x + (size_t)blockIdx.x * DCOLS);
    float4* __restrict__ orow =
        reinterpret_cast<float4*>(out + (size_t)blockIdx.x * DCOLS);

    __shared__ int      s_cnt[3][NW];  // [0]: bracket; [1]/[2] alternate per epoch
    __shared__ unsigned s_m[2 * NW];   // per-warp (M1,M2) keys for top-2
    __shared__ float    s_gain;
    __shared__ int      s_warp[NW];    // scan scratch (rare tie path)
    __shared__ float    s_small[CAP];  // epilogue candidate buffer
    __shared__ int      s_n;
    __shared__ float    s_T;
    __shared__ int      s_needed, s_eqc;

    // ---- load 8 values/thread, coalesced float4; branch-free top-2 ----
    float4 r0, r1;
    float m1 = -FLT_MAX, m2 = -FLT_MAX;
    r0 = xr[tid];
    r1 = xr[tid + NT];
    #define T2(v) { float _v = (v); m2 = fmaxf(m2, fminf(m1, _v)); m1 = fmaxf(m1, _v); }
    T2(r0.x) T2(r0.y) T2(r0.z) T2(r0.w)
    T2(r1.x) T2(r1.y) T2(r1.z) T2(r1.w)
    #undef T2

    // ---- warp top-2 (multiset) via REDUX on keys ----
    {
        unsigned k1 = f2k_f(m1), k2v = f2k_f(m2);
        unsigned M1 = __reduce_max_sync(0xFFFFFFFFu, k1);
        unsigned bal = __ballot_sync(0xFFFFFFFFu, k1 == M1);
        int leader = __ffs(bal) - 1;
        unsigned cand = (lane == leader) ? k2v : k1;
        unsigned M2 = __reduce_max_sync(0xFFFFFFFFu, cand);
        if (lane == 0) { s_m[2 * wid] = M1; s_m[2 * wid + 1] = M2; }
    }

    // ---- bracket: two wide probes (+-3.9 sigma), packed, one barrier ----
    const float PA = 0.95f, PB = 1.13f;   // threshold ~= 1.036 +- 0.024
    int cA, cB;
    CNT8_GE(PA, cA);
    CNT8_GE(PB, cB);
    {
        int pc = __reduce_add_sync(0xFFFFFFFFu, cA | (cB << 16));
        if (lane == 0) s_cnt[0][wid] = pc;
    }
    if (tid == 0) s_n = 0;
    __syncthreads();
    {
        int v;
        TREE16(s_cnt[0], v);
        cA = v & 0xFFFF; cB = v >> 16;
    }
    if (tid == 0) {
        unsigned a1 = s_m[0], a2 = s_m[1];
        #pragma unroll
        for (int w = 1; w < NW; w++) {
            unsigned b1 = s_m[2 * w], b2 = s_m[2 * w + 1];
            unsigned n1 = max(a1, b1);
            a2 = max(min(a1, b1), max(a2, b2));
            a1 = n1;
        }
        float d = k2f(a1) - k2f(a2);   // >= 0
        s_gain = GAIN_C / (1.0f + __expf(-d)) + 1.0f;
    }
    // s_gain read only after >=1 further barrier on every path.

    // ---- window select (block-uniform) ----
    float lo, hi; int clo, chi;
    if (cA >= KSEL && cB < KSEL)      { lo = PA;       clo = cA;    hi = PB;      chi = cB; }
    else if (cB >= KSEL)              { lo = PB;       clo = cB;    hi = FLT_MAX; chi = 0;  }
    else                              { lo = -FLT_MAX; clo = DCOLS; hi = PA;      chi = cA; }

    int active = clo - chi;
    int parity = 1;                 // epochs alternate buffers [1] and [2]
    bool resolved = false;
    float T = 0.0f; int needed = 0, eqc = 0;

    // ---- straight-line interpolation rounds (common path: 2) ----
    #pragma unroll
    for (int rr = 0; rr < 2; rr++) {
        if (active > CAP && !resolved) {           // block-uniform
            float fm = lo + (hi - lo) * ((float)(clo - KSEL) / (float)(clo - chi));
            if (!(fm > lo && fm < hi)) fm = 0.5f * (lo + hi);
            if (fm > lo && fm < hi) {
                int cm;
                CNT8_GE(fm, cm);
                cm = __reduce_add_sync(0xFFFFFFFFu, cm);
                if (lane == 0) s_cnt[parity][wid] = cm;
                __syncthreads();
                TREE16(s_cnt[parity], cm);
                parity = 3 - parity;
                if (cm >= KSEL) { lo = fm; clo = cm; } else { hi = fm; chi = cm; }
                active = clo - chi;
            } else {
                // interval degenerate (<=1 ulp): all window values equal lo
                resolved = true; T = lo; needed = KSEL - chi; eqc = active;
                __syncthreads();       // s_gain visibility on this path
            }
        }
    }

    // ---- rare fallback: exact uint-space descent ----
    if (active > CAP && !resolved) {
        unsigned ulo = f2k_f(lo), uhi = f2k_f(hi);
        int round = 0;
        while (active > CAP && uhi - ulo > 1u) {
            unsigned um;
            if (round & 1) {
                um = ulo + ((uhi - ulo) >> 1);
            } else {
                float t = lo + (hi - lo) * ((float)(clo - KSEL) / (float)(clo - chi));
                um = f2k_f(t);
                if (um <= ulo || um >= uhi) um = ulo + ((uhi - ulo) >> 1);
            }
            float fm = k2f(um);
            int cm;
            CNT8_GE(fm, cm);
            cm = __reduce_add_sync(0xFFFFFFFFu, cm);
            if (lane == 0) s_cnt[parity][wid] = cm;
            __syncthreads();
            TREE16(s_cnt[parity], cm);
            parity = 3 - parity;
            if (cm >= KSEL) { ulo = um; lo = fm; clo = cm; }
            else            { uhi = um; hi = fm; chi = cm; }
            active = clo - chi;
            round++;
        }
        if (active > CAP) {     // width-1 interval: all equal
            resolved = true; T = k2f(ulo); needed = KSEL - chi; eqc = active;
        }
    }

    if (!resolved) {
        // ---- epilogue: compact <=32 candidates in [lo,hi), rank on warp 0 ----
        #define PUT(v) { float _v = (v); if (_v >= lo && _v < hi) { \
                           int _p = atomicAdd(&s_n, 1); if (_p < CAP) s_small[_p] = _v; } }
        PUT(r0.x) PUT(r0.y) PUT(r0.z) PUT(r0.w)
        PUT(r1.x) PUT(r1.y) PUT(r1.z) PUT(r1.w)
        #undef PUT
        __syncthreads();
        if (wid == 0) {
            const int cnt = min(s_n, CAP);        // == active
            const int k_small = KSEL - chi;       // 1 <= k_small <= cnt
            float v = (lane < cnt) ? s_small[lane] : -FLT_MAX;
            int cgt = 0, cge = 0;
            #pragma unroll
            for (int j = 0; j < CAP; j++) {
                float w = __shfl_sync(0xFFFFFFFFu, v, j);
                bool valid = (j < cnt);
                cgt += valid && (w > v);
                cge += valid && (w >= v);
            }
            if (lane < cnt && cgt < k_small && k_small <= cge) {
                s_T = v;
                s_needed = k_small - cgt;         // # of ==T to include
                s_eqc = cge - cgt;                // total ==T in row
            }
        }
        __syncthreads();
        T = s_T; needed = s_needed; eqc = s_eqc;
    } else {
        __syncthreads();        // uniform; s_gain visibility
    }

    const bool use_rank = (needed != eqc);   // rare: partial tie at threshold

    // ---- rare path: rank ==T elements in exact column order ----
    // column(c) = i*2048 + tid*4 + j  -> order over (i, tid, j)
    int base0 = 0, base1 = 0;
    if (use_rank) {
        int chunkbase = 0;
        #pragma unroll
        for (int i = 0; i < 2; i++) {
            float4 q = (i == 0) ? r0 : r1;
            int c = (q.x == T) + (q.y == T) + (q.z == T) + (q.w == T);
            int incl = warp_incl_scan(c, lane);
            if (lane == 31) s_warp[wid] = incl;
            __syncthreads();
            if (wid == 0) {
                int w = (lane < NW) ? s_warp[lane] : 0;
                int wi = warp_incl_scan(w, lane);
                if (lane < NW) s_warp[lane] = wi;
            }
            __syncthreads();
            int offset = wid ? s_warp[wid - 1] : 0;
            int b = chunkbase + offset + incl - c;
            if (i == 0) base0 = b; else base1 = b;
            chunkbase += s_warp[NW - 1];
            __syncthreads();
        }
    }

    const float gain = s_gain;

    // ---- write pass: from registers (no 2nd global read) ----
    #pragma unroll
    for (int i = 0; i < 2; i++) {
        float4 q = (i == 0) ? r0 : r1;
        int rr_ = (i == 0) ? base0 : base1;
        float in[4] = { q.x, q.y, q.z, q.w };
        float o[4];
        #pragma unroll
        for (int j = 0; j < 4; j++) {
            float v = in[j];
            bool inc;
            if (!use_rank) {
                inc = (v >= T);
            } else {
                if (v > T) inc = true;
                else if (v == T) { inc = (rr_ < needed); rr_++; }
                else inc = false;
            }
            o[j] = inc ? (v * gain) : 0.0f;
        }
        orow[tid + i * NT] = make_float4(o[0], o[1], o[2], o[3]);
    }
}

extern "C" void kernel_launch(void* const* d_in, const int* in_sizes, int n_in,
                              void* d_out, int out_size) {
    const float* x = (const float*)d_in[0];
    float* out = (float*)d_out;
    int nrows = in_sizes[0] / DCOLS;
    diff_gated_topk_kernel<<<nrows, NT>>>(x, out);
}

// round 16
// speedup vs baseline: 1.4936x; 1.4936x over previous
#include <cuda_runtime.h>
#include <cstdint>
#include <float.h>

// DiffGatedTopK: x [N=16384, D=4096] fp32.
// k = int(D*0.15) = 614. out = x * topk_mask * (sigmoid(top1-top2)*3 + 1)

#define DCOLS 4096
#define KSEL  614
#define NT    256
#define GAIN_C 3.0f
#define CAP   32
#define NPROBE 10
#define PBASE  0.95f
#define PDELTA 0.02f     // P_j = 0.95 + 0.02*j, j=0..9 -> [0.95, 1.13]

// float <-> order-preserving unsigned key (fallback / top-2 reduce only)
__device__ __forceinline__ unsigned f2k_f(float f) {
    unsigned u = __float_as_uint(f);
    return u ^ ((unsigned)(((int)u) >> 31) | 0x80000000u);
}
__device__ __forceinline__ float k2f(unsigned k) {
    unsigned b = (k & 0x80000000u) ? (k ^ 0x80000000u) : ~k;
    return __uint_as_float(b);
}

__device__ __forceinline__ int warp_incl_scan(int v, int lane) {
    #pragma unroll
    for (int o = 1; o < 32; o <<= 1) {
        int n = __shfl_up_sync(0xFFFFFFFFu, v, o);
        if (lane >= o) v += n;
    }
    return v;
}

// cell index: # of probes <= v, clamped to [0, NPROBE].
// idx(v) = clamp((int)(v*50 - 46.5), 0, 10); monotone (FFMA+trunc monotone).
__device__ __forceinline__ int probe_idx(float v) {
    int i = (int)fmaf(v, 50.0f, -46.5f);
    return min(NPROBE, max(0, i));
}

// count of the 16 register-resident values >= t (guard path)
#define CNT16_GE(t, res) do {                                            \
    int _c = 0;                                                          \
    _c += (r0.x >= (t)) + (r0.y >= (t)) + (r0.z >= (t)) + (r0.w >= (t));\
    _c += (r1.x >= (t)) + (r1.y >= (t)) + (r1.z >= (t)) + (r1.w >= (t));\
    _c += (r2.x >= (t)) + (r2.y >= (t)) + (r2.z >= (t)) + (r2.w >= (t));\
    _c += (r3.x >= (t)) + (r3.y >= (t)) + (r3.z >= (t)) + (r3.w >= (t));\
    (res) = _c; } while (0)

// block reduce helper: tree over 8 per-warp partials stored in buf
#define TREE8(buf, res) do {                                             \
    int _v = (lane < 8) ? (buf)[lane] : 0;                               \
    _v += __shfl_down_sync(0xFFFFFFFFu, _v, 4);                          \
    _v += __shfl_down_sync(0xFFFFFFFFu, _v, 2);                          \
    _v += __shfl_down_sync(0xFFFFFFFFu, _v, 1);                          \
    (res) = __shfl_sync(0xFFFFFFFFu, _v, 0); } while (0)

__global__ void __launch_bounds__(NT, 6)
diff_gated_topk_kernel(const float* __restrict__ x, float* __restrict__ out) {
    const int tid  = threadIdx.x;
    const int lane = tid & 31;
    const int wid  = tid >> 5;

    const float4* __restrict__ xr =
        reinterpret_cast<const float4*>(x + (size_t)blockIdx.x * DCOLS);
    float4* __restrict__ orow =
        reinterpret_cast<float4*>(out + (size_t)blockIdx.x * DCOLS);

    __shared__ int      s_cnt[5][8];   // probe-fan partials; reused by guard path
    __shared__ unsigned s_m[16];       // per-warp (M1,M2) keys for top-2
    __shared__ float    s_gain;
    __shared__ int      s_warp[8];     // scan scratch (rare tie path)
    __shared__ float    s_small[CAP];  // epilogue candidate buffer
    __shared__ int      s_n;
    __shared__ float    s_T;
    __shared__ int      s_needed, s_eqc;

    // ---- load 16 values/thread, coalesced float4; branch-free top-2 ----
    float4 r0, r1, r2, r3;
    float m1 = -FLT_MAX, m2 = -FLT_MAX;
    r0 = xr[tid];            r1 = xr[tid + NT];
    r2 = xr[tid + 2 * NT];   r3 = xr[tid + 3 * NT];
    #define T2(v) { float _v = (v); m2 = fmaxf(m2, fminf(m1, _v)); m1 = fmaxf(m1, _v); }
    T2(r0.x) T2(r0.y) T2(r0.z) T2(r0.w)
    T2(r1.x) T2(r1.y) T2(r1.z) T2(r1.w)
    T2(r2.x) T2(r2.y) T2(r2.z) T2(r2.w)
    T2(r3.x) T2(r3.y) T2(r3.z) T2(r3.w)
    #undef T2

    // ---- warp top-2 (multiset) via REDUX on keys ----
    {
        unsigned k1 = f2k_f(m1), k2v = f2k_f(m2);
        unsigned M1 = __reduce_max_sync(0xFFFFFFFFu, k1);
        unsigned bal = __ballot_sync(0xFFFFFFFFu, k1 == M1);
        int leader = __ffs(bal) - 1;
        unsigned cand = (lane == leader) ? k2v : k1;
        unsigned M2 = __reduce_max_sync(0xFFFFFFFFu, cand);
        if (lane == 0) { s_m[2 * wid] = M1; s_m[2 * wid + 1] = M2; }
    }

    // ---- 10-probe fan, single epoch: 64-bit nibble histogram ----
    unsigned long long accA = 0ull, accB = 0ull;
    #define ACC1(acc, v) { int _i = probe_idx(v); \
        (acc) += ((1ull << (4 * _i)) - 1ull) & 0x1111111111ull; }
    ACC1(accA, r0.x) ACC1(accA, r0.y) ACC1(accA, r0.z) ACC1(accA, r0.w)
    ACC1(accA, r1.x) ACC1(accA, r1.y) ACC1(accA, r1.z) ACC1(accA, r1.w)
    ACC1(accB, r2.x) ACC1(accB, r2.y) ACC1(accB, r2.z) ACC1(accB, r2.w)
    ACC1(accB, r3.x) ACC1(accB, r3.y) ACC1(accB, r3.z) ACC1(accB, r3.w)
    #undef ACC1
    {
        #pragma unroll
        for (int p = 0; p < 5; p++) {
            int cl = (int)((accA >> (8 * p)) & 0xFull) + (int)((accB >> (8 * p)) & 0xFull);
            int ch = (int)((accA >> (8 * p + 4)) & 0xFull) + (int)((accB >> (8 * p + 4)) & 0xFull);
            int pw = __reduce_add_sync(0xFFFFFFFFu, cl | (ch << 16));
            if (lane == 0) s_cnt[p][wid] = pw;
        }
    }
    if (tid == 0) s_n = 0;
    __syncthreads();

    int cblk[NPROBE];
    {
        #pragma unroll
        for (int p = 0; p < 5; p++) {
            int v;
            TREE8(s_cnt[p], v);
            cblk[2 * p] = v & 0xFFFF;
            cblk[2 * p + 1] = v >> 16;
        }
    }
    if (tid == 0) {
        unsigned a1 = s_m[0], a2 = s_m[1];
        #pragma unroll
        for (int w = 1; w < 8; w++) {
            unsigned b1 = s_m[2 * w], b2 = s_m[2 * w + 1];
            unsigned n1 = max(a1, b1);
            a2 = max(min(a1, b1), max(a2, b2));
            a1 = n1;
        }
        float d = k2f(a1) - k2f(a2);   // >= 0
        s_gain = GAIN_C / (1.0f + __expf(-d)) + 1.0f;
    }
    // s_gain read only after >=1 further barrier on every path.

    // ---- cell selection (block-uniform) ----
    int jstar = -1;
    #pragma unroll
    for (int j = 0; j < NPROBE; j++) if (cblk[j] >= KSEL) jstar = j;

    int clo, chiv;
    if (jstar < 0)                 { clo = DCOLS;        chiv = cblk[0]; }
    else if (jstar == NPROBE - 1)  { clo = cblk[jstar];  chiv = 0; }
    else                           { clo = cblk[jstar];  chiv = cblk[jstar + 1]; }
    const int cw = jstar + 1;                 // selected cell index value
    int cellcount = clo - chiv;

    float T = 0.0f; int needed = 0, eqc = 0;

    if (cellcount <= CAP) {
        // ---- common path: epilogue directly (2nd and last epoch) ----
        #define PUTI(v) { float _v = (v); if (probe_idx(_v) == cw) { \
                            int _p = atomicAdd(&s_n, 1); if (_p < CAP) s_small[_p] = _v; } }
        PUTI(r0.x) PUTI(r0.y) PUTI(r0.z) PUTI(r0.w)
        PUTI(r1.x) PUTI(r1.y) PUTI(r1.z) PUTI(r1.w)
        PUTI(r2.x) PUTI(r2.y) PUTI(r2.z) PUTI(r2.w)
        PUTI(r3.x) PUTI(r3.y) PUTI(r3.z) PUTI(r3.w)
        #undef PUTI
        __syncthreads();
        if (wid == 0) {
            const int cnt = cellcount;            // exact by construction
            const int k_small = KSEL - chiv;      // 1 <= k_small <= cnt
            float v = (lane < cnt) ? s_small[lane] : -FLT_MAX;
            int cgt = 0, cge = 0;
            #pragma unroll
            for (int j = 0; j < CAP; j++) {
                float w = __shfl_sync(0xFFFFFFFFu, v, j);
                bool valid = (j < cnt);
                cgt += valid && (w > v);
                cge += valid && (w >= v);
            }
            if (lane < cnt && cgt < k_small && k_small <= cge) {
                s_T = v;
                s_needed = k_small - cgt;         // # of ==T to include
                s_eqc = cge - cgt;                // total ==T in row
            }
        }
        __syncthreads();
        T = s_T; needed = s_needed; eqc = s_eqc;
    } else {
        // ---- guard path (~1%): exact compare-based machinery ----
        float lo = (jstar < 0) ? -FLT_MAX : (PBASE + PDELTA * jstar);
        float hi = (jstar == NPROBE - 1) ? FLT_MAX : (PBASE + PDELTA * (jstar + 1));

        // exact packed re-bracket at (lo, hi)
        int cA, cB;
        CNT16_GE(lo, cA);
        CNT16_GE(hi, cB);
        {
            int pc = __reduce_add_sync(0xFFFFFFFFu, cA | (cB << 16));
            if (lane == 0) s_cnt[0][wid] = pc;
        }
        __syncthreads();
        {
            int v;
            TREE8(s_cnt[0], v);
            cA = v & 0xFFFF; cB = v >> 16;
        }
        int chi;
        if (cB >= KSEL)      { lo = hi; clo = cB; hi = FLT_MAX; chi = 0; }
        else if (cA < KSEL)  { hi = lo; chi = cA; lo = -FLT_MAX; clo = DCOLS; }
        else                 { clo = cA; chi = cB; }

        int active = clo - chi;
        int parity = 1;
        bool resolved = false;

        #pragma unroll
        for (int rr = 0; rr < 2; rr++) {
            if (active > CAP && !resolved) {
                float fm = lo + (hi - lo) * ((float)(clo - KSEL) / (float)(clo - chi));
                if (!(fm > lo && fm < hi)) fm = 0.5f * (lo + hi);
                if (fm > lo && fm < hi) {
                    int cm;
                    CNT16_GE(fm, cm);
                    cm = __reduce_add_sync(0xFFFFFFFFu, cm);
                    if (lane == 0) s_cnt[parity][wid] = cm;
                    __syncthreads();
                    TREE8(s_cnt[parity], cm);
                    parity = 3 - parity;
                    if (cm >= KSEL) { lo = fm; clo = cm; } else { hi = fm; chi = cm; }
                    active = clo - chi;
                } else {
                    resolved = true; T = lo; needed = KSEL - chi; eqc = active;
                    __syncthreads();
                }
            }
        }

        if (active > CAP && !resolved) {
            unsigned ulo = f2k_f(lo), uhi = f2k_f(hi);
            int round = 0;
            while (active > CAP && uhi - ulo > 1u) {
                unsigned um;
                if (round & 1) {
                    um = ulo + ((uhi - ulo) >> 1);
                } else {
                    float t = lo + (hi - lo) * ((float)(clo - KSEL) / (float)(clo - chi));
                    um = f2k_f(t);
                    if (um <= ulo || um >= uhi) um = ulo + ((uhi - ulo) >> 1);
                }
                float fm = k2f(um);
                int cm;
                CNT16_GE(fm, cm);
                cm = __reduce_add_sync(0xFFFFFFFFu, cm);
                if (lane == 0) s_cnt[parity][wid] = cm;
                __syncthreads();
                TREE8(s_cnt[parity], cm);
                parity = 3 - parity;
                if (cm >= KSEL) { ulo = um; lo = fm; clo = cm; }
                else            { uhi = um; hi = fm; chi = cm; }
                active = clo - chi;
                round++;
            }
            if (active > CAP) {
                resolved = true; T = k2f(ulo); needed = KSEL - chi; eqc = active;
            }
        }

        if (!resolved) {
            #define PUT(v) { float _v = (v); if (_v >= lo && _v < hi) { \
                               int _p = atomicAdd(&s_n, 1); if (_p < CAP) s_small[_p] = _v; } }
            PUT(r0.x) PUT(r0.y) PUT(r0.z) PUT(r0.w)
            PUT(r1.x) PUT(r1.y) PUT(r1.z) PUT(r1.w)
            PUT(r2.x) PUT(r2.y) PUT(r2.z) PUT(r2.w)
            PUT(r3.x) PUT(r3.y) PUT(r3.z) PUT(r3.w)
            #undef PUT
            __syncthreads();
            if (wid == 0) {
                const int cnt = min(s_n, CAP);
                const int k_small = KSEL - chi;
                float v = (lane < cnt) ? s_small[lane] : -FLT_MAX;
                int cgt = 0, cge = 0;
                #pragma unroll
                for (int j = 0; j < CAP; j++) {
                    float w = __shfl_sync(0xFFFFFFFFu, v, j);
                    bool valid = (j < cnt);
                    cgt += valid && (w > v);
                    cge += valid && (w >= v);
                }
                if (lane < cnt && cgt < k_small && k_small <= cge) {
                    s_T = v;
                    s_needed = k_small - cgt;
                    s_eqc = cge - cgt;
                }
            }
            __syncthreads();
            T = s_T; needed = s_needed; eqc = s_eqc;
        } else {
            __syncthreads();
        }
    }

    const bool use_rank = (needed != eqc);   // rare: partial tie at threshold

    // ---- rare path: rank ==T elements in exact column order ----
    // column(c) = i*1024 + tid*4 + j  -> order over (i, tid, j)
    int base0 = 0, base1 = 0, base2 = 0, base3 = 0;
    if (use_rank) {
        int chunkbase = 0;
        #pragma unroll
        for (int i = 0; i < 4; i++) {
            float4 q = (i == 0) ? r0 : (i == 1) ? r1 : (i == 2) ? r2 : r3;
            int c = (q.x == T) + (q.y == T) + (q.z == T) + (q.w == T);
            int incl = warp_incl_scan(c, lane);
            if (lane == 31) s_warp[wid] = incl;
            __syncthreads();
            if (wid == 0) {
                int w = (lane < 8) ? s_warp[lane] : 0;
                int wi = warp_incl_scan(w, lane);
                if (lane < 8) s_warp[lane] = wi;
            }
            __syncthreads();
            int offset = wid ? s_warp[wid - 1] : 0;
            int b = chunkbase + offset + incl - c;
            if (i == 0) base0 = b; else if (i == 1) base1 = b;
            else if (i == 2) base2 = b; else base3 = b;
            chunkbase += s_warp[7];
            __syncthreads();
        }
    }

    const float gain = s_gain;

    // ---- write pass: from registers (no 2nd global read) ----
    #pragma unroll
    for (int i = 0; i < 4; i++) {
        float4 q = (i == 0) ? r0 : (i == 1) ? r1 : (i == 2) ? r2 : r3;
        int rr_ = (i == 0) ? base0 : (i == 1) ? base1 : (i == 2) ? base2 : base3;
        float in[4] = { q.x, q.y, q.z, q.w };
        float o[4];
        #pragma unroll
        for (int j = 0; j < 4; j++) {
            float v = in[j];
            bool inc;
            if (!use_rank) {
                inc = (v >= T);
            } else {
                if (v > T) inc = true;
                else if (v == T) { inc = (rr_ < needed); rr_++; }
                else inc = false;
            }
            o[j] = inc ? (v * gain) : 0.0f;
        }
        orow[tid + i * NT] = make_float4(o[0], o[1], o[2], o[3]);
    }
}

extern "C" void kernel_launch(void* const* d_in, const int* in_sizes, int n_in,
                              void* d_out, int out_size) {
    const float* x = (const float*)d_in[0];
    float* out = (float*)d_out;
    int nrows = in_sizes[0] / DCOLS;
    diff_gated_topk_kernel<<<nrows, NT>>>(x, out);
}